// round 4
// baseline (speedup 1.0000x reference)
#include <cuda_runtime.h>
#include <cstdint>

// GCN on complete graph + self-loops == per-batch mean pooling -> per-batch
// 4-layer MLP on the mean node feature. TMA-staged weights, 512 threads
// (4 warps/SMSP), dense layers k-split across two thread groups with a
// float4 smem partial reduce; packed fma.rn.f32x2 accumulators.

#define ROWS 8
#define NT   512

// ---- smem layout (floats) ----
#define OFF_OBS   0
#define N_OBS     (ROWS * 512)          // 4096 (reused as partial scratch)
#define OFF_P     OFF_OBS               // partial scratch (2048 floats needed)
#define OFF_W1    (OFF_OBS + N_OBS)
#define N_W1      (14 * 128)
#define OFF_B1    (OFF_W1 + N_W1)
#define OFF_W2    (OFF_B1 + 128)
#define N_W2      (128 * 128)
#define OFF_B2    (OFF_W2 + N_W2)
#define OFF_WM1   (OFF_B2 + 128)
#define OFF_BM1   (OFF_WM1 + N_W2)
#define OFF_WM2   (OFF_BM1 + 128)
#define N_WM2     (128 * 4)
#define OFF_BM2   (OFF_WM2 + N_WM2)
#define OFF_A     (OFF_BM2 + 4)
#define OFF_B     (OFF_A + ROWS * 128)
#define OFF_F     (OFF_B + ROWS * 128)
#define OFF_MBAR  (OFF_F + ROWS * 16)
#define SMEM_FLOATS (OFF_MBAR + 8)
#define SMEM_BYTES  (SMEM_FLOATS * 4)

#define BYTES_A ((N_OBS + N_W1 + 128) * 4)
#define BYTES_B ((N_W2 + 128) * 4)
#define BYTES_C ((N_W2 + 128 + N_WM2 + 4) * 4)

__device__ __forceinline__ uint32_t s2u(const void* p) {
    return (uint32_t)__cvta_generic_to_shared(p);
}
__device__ __forceinline__ void mbar_init(uint32_t a, uint32_t cnt) {
    asm volatile("mbarrier.init.shared.b64 [%0], %1;" :: "r"(a), "r"(cnt) : "memory");
}
__device__ __forceinline__ void mbar_expect(uint32_t a, uint32_t bytes) {
    asm volatile("mbarrier.arrive.expect_tx.shared.b64 _, [%0], %1;"
                 :: "r"(a), "r"(bytes) : "memory");
}
__device__ __forceinline__ void bulk_g2s(uint32_t dst, const void* src,
                                         uint32_t bytes, uint32_t mbar) {
    asm volatile("cp.async.bulk.shared::cluster.global.mbarrier::complete_tx::bytes "
                 "[%0], [%1], %2, [%3];"
                 :: "r"(dst), "l"(src), "r"(bytes), "r"(mbar) : "memory");
}
__device__ __forceinline__ void mbar_wait(uint32_t a, uint32_t parity) {
    asm volatile(
        "{\n\t.reg .pred P;\n"
        "WAIT_%=:\n\t"
        "mbarrier.try_wait.parity.shared.b64 P, [%0], %1, 0x989680;\n\t"
        "@P bra.uni DONE_%=;\n\t"
        "bra.uni WAIT_%=;\n"
        "DONE_%=:\n\t}"
        :: "r"(a), "r"(parity) : "memory");
}

// ---- packed f32x2 helpers ----
__device__ __forceinline__ unsigned long long pk(float x, float y) {
    unsigned long long r;
    asm("mov.b64 %0, {%1, %2};" : "=l"(r) : "f"(x), "f"(y));
    return r;
}
__device__ __forceinline__ void fma2(unsigned long long& c,
                                     unsigned long long a, unsigned long long b) {
    asm("fma.rn.f32x2 %0, %1, %2, %3;" : "=l"(c) : "l"(a), "l"(b), "l"(c));
}

// Dense 128->128 with k-split.
// Activation layout: pair p (rows 2p,2p+1): sIn[p*256 + 2k + e] = act[2p+e][k].
// Thread: col = tid&127, h = (tid>>7)&1 (pairs 2h,2h+1), ks = tid>>8 (k half).
// Partials in sP (float4 per thread), reduced by tid<256.
__device__ __forceinline__ void dense128s(const float* __restrict__ sIn,
                                          const float* __restrict__ sW,
                                          const float* __restrict__ sb,
                                          float* __restrict__ sOut,
                                          float* __restrict__ sP, int tid) {
    const int col = tid & 127;
    const int h   = (tid >> 7) & 1;
    const int ks  = tid >> 8;

    unsigned long long accA = 0ULL, accB = 0ULL;   // (0.f, 0.f)
    const ulonglong2* inA =
        reinterpret_cast<const ulonglong2*>(sIn + (2 * h) * 256 + ks * 128);
    const ulonglong2* inB =
        reinterpret_cast<const ulonglong2*>(sIn + (2 * h + 1) * 256 + ks * 128);
    const float* wB = sW + (ks * 64) * 128 + col;

    #pragma unroll
    for (int kq = 0; kq < 16; kq++) {
        const float w0 = wB[(4 * kq + 0) * 128];
        const float w1 = wB[(4 * kq + 1) * 128];
        const float w2 = wB[(4 * kq + 2) * 128];
        const float w3 = wB[(4 * kq + 3) * 128];
        const unsigned long long wp0 = pk(w0, w0);
        const unsigned long long wp1 = pk(w1, w1);
        const unsigned long long wp2 = pk(w2, w2);
        const unsigned long long wp3 = pk(w3, w3);
        const ulonglong2 a0 = inA[2 * kq], a1 = inA[2 * kq + 1];
        const ulonglong2 b0 = inB[2 * kq], b1 = inB[2 * kq + 1];
        fma2(accA, a0.x, wp0); fma2(accA, a0.y, wp1);
        fma2(accA, a1.x, wp2); fma2(accA, a1.y, wp3);
        fma2(accB, b0.x, wp0); fma2(accB, b0.y, wp1);
        fma2(accB, b1.x, wp2); fma2(accB, b1.y, wp3);
    }
    // store partials (float4 per thread)
    float2 pa = *reinterpret_cast<float2*>(&accA);
    float2 pb = *reinterpret_cast<float2*>(&accB);
    reinterpret_cast<float4*>(sP)[tid] = make_float4(pa.x, pa.y, pb.x, pb.y);
    __syncthreads();

    if (tid < 256) {
        const int c2 = tid & 127, h2 = tid >> 7;
        const float4 x = reinterpret_cast<const float4*>(sP)[tid];
        const float4 y = reinterpret_cast<const float4*>(sP)[tid + 256];
        const float bb = sb[c2];
        float2 vA = make_float2(fmaxf(x.x + y.x + bb, 0.f),
                                fmaxf(x.y + y.y + bb, 0.f));
        float2 vB = make_float2(fmaxf(x.z + y.z + bb, 0.f),
                                fmaxf(x.w + y.w + bb, 0.f));
        reinterpret_cast<float2*>(sOut)[(2 * h2) * 128 + c2]     = vA;
        reinterpret_cast<float2*>(sOut)[(2 * h2 + 1) * 128 + c2] = vB;
    }
    __syncthreads();
}

__global__ __launch_bounds__(NT) void gcnn_actor_kernel(
    const float* __restrict__ obs,
    const float* __restrict__ W1,  const float* __restrict__ b1,
    const float* __restrict__ W2,  const float* __restrict__ b2,
    const float* __restrict__ Wm1, const float* __restrict__ bm1,
    const float* __restrict__ Wm2, const float* __restrict__ bm2,
    float* __restrict__ out, int std_off)
{
    extern __shared__ float sm[];
    float* sObs = sm + OFF_OBS;
    float* sP   = sm + OFF_P;
    float* sA   = sm + OFF_A;
    float* sB   = sm + OFF_B;
    float* sF   = sm + OFF_F;

    const int tid  = threadIdx.x;
    const int col  = tid & 127;
    const int base = blockIdx.x * ROWS;

    const uint32_t mbarA = s2u(sm + OFF_MBAR);
    const uint32_t mbarB = mbarA + 8;
    const uint32_t mbarC = mbarA + 16;

    if (tid == 0) { mbar_init(mbarA, 1); mbar_init(mbarB, 1); mbar_init(mbarC, 1); }
    __syncthreads();

    if (tid == 0) {
        mbar_expect(mbarA, BYTES_A);
        bulk_g2s(s2u(sm + OFF_OBS), obs + (size_t)base * 512, N_OBS * 4, mbarA);
        bulk_g2s(s2u(sm + OFF_W1),  W1,  N_W1 * 4,  mbarA);
        bulk_g2s(s2u(sm + OFF_B1),  b1,  128 * 4,   mbarA);
        mbar_expect(mbarB, BYTES_B);
        bulk_g2s(s2u(sm + OFF_W2),  W2,  N_W2 * 4,  mbarB);
        bulk_g2s(s2u(sm + OFF_B2),  b2,  128 * 4,   mbarB);
        mbar_expect(mbarC, BYTES_C);
        bulk_g2s(s2u(sm + OFF_WM1), Wm1, N_W2 * 4,  mbarC);
        bulk_g2s(s2u(sm + OFF_BM1), bm1, 128 * 4,   mbarC);
        bulk_g2s(s2u(sm + OFF_WM2), Wm2, N_WM2 * 4, mbarC);
        bulk_g2s(s2u(sm + OFF_BM2), bm2, 4 * 4,     mbarC);
    }

    // ---- obs + layer-1 params ----
    mbar_wait(mbarA, 0);

    // fbar[r][d] = mean over 32 nodes of obs[., n*16 + 2 + d]
    if (tid < ROWS * 14) {
        const int r = tid / 14, d = tid % 14;
        float s = 0.f;
        #pragma unroll
        for (int n = 0; n < 32; n++) s += sObs[r * 512 + n * 16 + 2 + d];
        sF[r * 16 + d] = s * (1.0f / 32.0f);
    }
    __syncthreads();

    // h1 = relu(fbar @ W1 + b1) -> sA (row-pair packed). Thread: pair p = tid>>7.
    {
        const int p = tid >> 7;           // 0..3, rows 2p, 2p+1
        float w[14];
        #pragma unroll
        for (int d = 0; d < 14; d++) w[d] = sm[OFF_W1 + d * 128 + col];
        const float bb = sm[OFF_B1 + col];
        float a0 = bb, a1 = bb;
        #pragma unroll
        for (int d = 0; d < 14; d++) {
            a0 = fmaf(sF[(2 * p) * 16 + d],     w[d], a0);
            a1 = fmaf(sF[(2 * p + 1) * 16 + d], w[d], a1);
        }
        reinterpret_cast<float2*>(sA)[p * 128 + col] =
            make_float2(fmaxf(a0, 0.f), fmaxf(a1, 0.f));
    }

    mbar_wait(mbarB, 0);
    __syncthreads();

    // h2 = relu(h1 @ W2 + b2) : sA -> sB
    dense128s(sA, sm + OFF_W2, sm + OFF_B2, sB, sP, tid);

    mbar_wait(mbarC, 0);

    // m = relu(h2 @ Wm1 + bm1) : sB -> sA
    dense128s(sB, sm + OFF_WM1, sm + OFF_BM1, sA, sP, tid);

    // o = m @ Wm2 + bm2 : 512 threads = 8 rows x 4 cols x 16 k-slices of 8
    {
        const int r = tid >> 6, c = (tid >> 4) & 3, s = tid & 15;
        const int pair = r >> 1, e = r & 1;
        float p = 0.f;
        #pragma unroll
        for (int i = 0; i < 8; i++) {
            const int k = s * 8 + i;
            p = fmaf(sA[pair * 256 + 2 * k + e], sm[OFF_WM2 + k * 4 + c], p);
        }
        sP[tid] = p;
    }
    __syncthreads();
    if (tid < ROWS * 4) {
        const int r = tid >> 2, c = tid & 3;
        float o = sm[OFF_BM2 + c];
        #pragma unroll
        for (int s = 0; s < 16; s++) o += sP[r * 64 + c * 16 + s];
        sF[r * 16 + c] = o;
    }
    __syncthreads();

    // write: mu replicated x32, std = exp(-5 + 3.5*(tanh(o)+1)) replicated x32
    #pragma unroll
    for (int i = tid; i < ROWS * 128; i += NT) {
        const int r = i >> 7, j = i & 127;
        const size_t b = (size_t)(base + r);
        if (j < 64) {
            out[b * 64 + j] = sF[r * 16 + (j & 1)];
        } else {
            const int jj = j - 64;
            const float lc = sF[r * 16 + 2 + (jj & 1)];
            const float t  = tanhf(lc);
            out[(size_t)std_off + b * 64 + jj] = __expf(-5.0f + 3.5f * (t + 1.0f));
        }
    }
}

extern "C" void kernel_launch(void* const* d_in, const int* in_sizes, int n_in,
                              void* d_out, int out_size) {
    const float* obs = (const float*)d_in[0];
    const float* W1  = (const float*)d_in[1];
    const float* b1  = (const float*)d_in[2];
    const float* W2  = (const float*)d_in[3];
    const float* b2  = (const float*)d_in[4];
    const float* Wm1 = (const float*)d_in[5];
    const float* bm1 = (const float*)d_in[6];
    const float* Wm2 = (const float*)d_in[7];
    const float* bm2 = (const float*)d_in[8];
    float* out = (float*)d_out;

    const int bs = in_sizes[0] / 512;
    const int std_off = bs * 64;
    const int grid = bs / ROWS;

    cudaFuncSetAttribute(gcnn_actor_kernel,
                         cudaFuncAttributeMaxDynamicSharedMemorySize, SMEM_BYTES);
    gcnn_actor_kernel<<<grid, NT, SMEM_BYTES>>>(obs, W1, b1, W2, b2, Wm1, bm1,
                                                Wm2, bm2, out, std_off);
}

// round 5
// speedup vs baseline: 1.1221x; 1.1221x over previous
#include <cuda_runtime.h>
#include <cstdint>

// GCN on complete graph + self-loops == per-batch mean pooling -> per-batch
// 4-layer MLP on the mean node feature. TMA-staged weights (W2 split in two
// chunks for load/compute overlap), 256 threads, manually software-pipelined
// dense loops with packed fma.rn.f32x2 accumulators.

#define ROWS 8
#define NT   256

typedef unsigned long long ull;

// ---- smem layout (floats) ----
#define OFF_OBS   0
#define N_OBS     (ROWS * 512)
#define OFF_P     OFF_OBS               // scratch after obs is dead
#define OFF_W1    (OFF_OBS + N_OBS)
#define N_W1      (14 * 128)
#define OFF_B1    (OFF_W1 + N_W1)
#define OFF_W2    (OFF_B1 + 128)
#define N_W2      (128 * 128)
#define OFF_B2    (OFF_W2 + N_W2)
#define OFF_WM1   (OFF_B2 + 128)
#define OFF_BM1   (OFF_WM1 + N_W2)
#define OFF_WM2   (OFF_BM1 + 128)
#define N_WM2     (128 * 4)
#define OFF_BM2   (OFF_WM2 + N_WM2)
#define OFF_A     (OFF_BM2 + 4)
#define OFF_B     (OFF_A + ROWS * 128)
#define OFF_F     (OFF_B + ROWS * 128)
#define OFF_MBAR  (OFF_F + ROWS * 16)   // 4 x u64
#define SMEM_FLOATS (OFF_MBAR + 8)
#define SMEM_BYTES  (SMEM_FLOATS * 4)

#define BYTES_A  ((N_OBS + N_W1 + 128) * 4)          // obs + W1 + b1
#define BYTES_B0 ((64 * 128) * 4)                    // W2 rows 0..63
#define BYTES_B1 ((64 * 128 + 128) * 4)              // W2 rows 64..127 + b2
#define BYTES_C  ((N_W2 + 128 + N_WM2 + 4) * 4)      // Wm1 + bm1 + Wm2 + bm2

__device__ __forceinline__ uint32_t s2u(const void* p) {
    return (uint32_t)__cvta_generic_to_shared(p);
}
__device__ __forceinline__ void mbar_init(uint32_t a, uint32_t cnt) {
    asm volatile("mbarrier.init.shared.b64 [%0], %1;" :: "r"(a), "r"(cnt) : "memory");
}
__device__ __forceinline__ void mbar_expect(uint32_t a, uint32_t bytes) {
    asm volatile("mbarrier.arrive.expect_tx.shared.b64 _, [%0], %1;"
                 :: "r"(a), "r"(bytes) : "memory");
}
__device__ __forceinline__ void bulk_g2s(uint32_t dst, const void* src,
                                         uint32_t bytes, uint32_t mbar) {
    asm volatile("cp.async.bulk.shared::cluster.global.mbarrier::complete_tx::bytes "
                 "[%0], [%1], %2, [%3];"
                 :: "r"(dst), "l"(src), "r"(bytes), "r"(mbar) : "memory");
}
__device__ __forceinline__ void mbar_wait(uint32_t a, uint32_t parity) {
    asm volatile(
        "{\n\t.reg .pred P;\n"
        "WAIT_%=:\n\t"
        "mbarrier.try_wait.parity.shared.b64 P, [%0], %1, 0x989680;\n\t"
        "@P bra.uni DONE_%=;\n\t"
        "bra.uni WAIT_%=;\n"
        "DONE_%=:\n\t}"
        :: "r"(a), "r"(parity) : "memory");
}

// ---- packed f32x2 helpers ----
__device__ __forceinline__ ull pk(float x, float y) {
    ull r;
    asm("mov.b64 %0, {%1, %2};" : "=l"(r) : "f"(x), "f"(y));
    return r;
}
__device__ __forceinline__ void fma2(ull& c, ull a, ull b) {
    asm("fma.rn.f32x2 %0, %1, %2, %3;" : "=l"(c) : "l"(a), "l"(b), "l"(c));
}
__device__ __forceinline__ float2 upk(ull v) {
    float2 r;
    asm("mov.b64 {%0, %1}, %2;" : "=f"(r.x), "=f"(r.y) : "l"(v));
    return r;
}

// Software-pipelined dense chunk over kq in [kqStart, kqStart+KQ).
// Activation layout: pair p: sIn[p*256 + 2k + e] = act[row 2p+e][k].
// wCol = sW + kqStart*4*128 + col.
template<int KQ>
__device__ __forceinline__ void dense_chunk(const ulonglong2* __restrict__ inA,
                                            const ulonglong2* __restrict__ inB,
                                            const float* __restrict__ wCol,
                                            int kqStart, ull& accA, ull& accB) {
    float w0, w1, w2, w3;
    ulonglong2 a0, a1, b0, b1;
    // preload iteration 0
    w0 = wCol[0]; w1 = wCol[128]; w2 = wCol[256]; w3 = wCol[384];
    a0 = inA[2 * kqStart];     a1 = inA[2 * kqStart + 1];
    b0 = inB[2 * kqStart];     b1 = inB[2 * kqStart + 1];
    #pragma unroll
    for (int i = 0; i < KQ; i++) {
        float nw0, nw1, nw2, nw3;
        ulonglong2 na0, na1, nb0, nb1;
        if (i + 1 < KQ) {
            const float* wP = wCol + (i + 1) * 512;
            nw0 = wP[0]; nw1 = wP[128]; nw2 = wP[256]; nw3 = wP[384];
            const int kn = kqStart + i + 1;
            na0 = inA[2 * kn]; na1 = inA[2 * kn + 1];
            nb0 = inB[2 * kn]; nb1 = inB[2 * kn + 1];
        }
        const ull wp0 = pk(w0, w0), wp1 = pk(w1, w1);
        const ull wp2 = pk(w2, w2), wp3 = pk(w3, w3);
        fma2(accA, a0.x, wp0); fma2(accA, a0.y, wp1);
        fma2(accA, a1.x, wp2); fma2(accA, a1.y, wp3);
        fma2(accB, b0.x, wp0); fma2(accB, b0.y, wp1);
        fma2(accB, b1.x, wp2); fma2(accB, b1.y, wp3);
        if (i + 1 < KQ) {
            w0 = nw0; w1 = nw1; w2 = nw2; w3 = nw3;
            a0 = na0; a1 = na1; b0 = nb0; b1 = nb1;
        }
    }
}

__global__ __launch_bounds__(NT) void gcnn_actor_kernel(
    const float* __restrict__ obs,
    const float* __restrict__ W1,  const float* __restrict__ b1,
    const float* __restrict__ W2,  const float* __restrict__ b2,
    const float* __restrict__ Wm1, const float* __restrict__ bm1,
    const float* __restrict__ Wm2, const float* __restrict__ bm2,
    float* __restrict__ out, int std_off)
{
    extern __shared__ float sm[];
    float* sObs = sm + OFF_OBS;
    float* sP   = sm + OFF_P;
    float* sA   = sm + OFF_A;
    float* sB   = sm + OFF_B;
    float* sF   = sm + OFF_F;

    const int tid  = threadIdx.x;
    const int col  = tid & 127;
    const int h    = tid >> 7;          // 0/1: row pairs 2h, 2h+1
    const int base = blockIdx.x * ROWS;

    const uint32_t mbarA  = s2u(sm + OFF_MBAR);
    const uint32_t mbarB0 = mbarA + 8;
    const uint32_t mbarB1 = mbarA + 16;
    const uint32_t mbarC  = mbarA + 24;

    if (tid == 0) {
        mbar_init(mbarA, 1); mbar_init(mbarB0, 1);
        mbar_init(mbarB1, 1); mbar_init(mbarC, 1);
    }
    __syncthreads();

    if (tid == 0) {
        mbar_expect(mbarA, BYTES_A);
        bulk_g2s(s2u(sm + OFF_OBS), obs + (size_t)base * 512, N_OBS * 4, mbarA);
        bulk_g2s(s2u(sm + OFF_W1),  W1,  N_W1 * 4,  mbarA);
        bulk_g2s(s2u(sm + OFF_B1),  b1,  128 * 4,   mbarA);
        mbar_expect(mbarB0, BYTES_B0);
        bulk_g2s(s2u(sm + OFF_W2),  W2,  64 * 128 * 4, mbarB0);
        mbar_expect(mbarB1, BYTES_B1);
        bulk_g2s(s2u(sm + OFF_W2 + 64 * 128), W2 + 64 * 128, 64 * 128 * 4, mbarB1);
        bulk_g2s(s2u(sm + OFF_B2),  b2,  128 * 4,   mbarB1);
        mbar_expect(mbarC, BYTES_C);
        bulk_g2s(s2u(sm + OFF_WM1), Wm1, N_W2 * 4,  mbarC);
        bulk_g2s(s2u(sm + OFF_BM1), bm1, 128 * 4,   mbarC);
        bulk_g2s(s2u(sm + OFF_WM2), Wm2, N_WM2 * 4, mbarC);
        bulk_g2s(s2u(sm + OFF_BM2), bm2, 4 * 4,     mbarC);
    }

    // ---- obs + layer-1 params ----
    mbar_wait(mbarA, 0);

    // fbar[r][d] = mean over 32 nodes of obs[., n*16 + 2 + d]
    if (tid < ROWS * 14) {
        const int r = tid / 14, d = tid % 14;
        float s = 0.f;
        #pragma unroll
        for (int n = 0; n < 32; n++) s += sObs[r * 512 + n * 16 + 2 + d];
        sF[r * 16 + d] = s * (1.0f / 32.0f);
    }
    __syncthreads();

    // h1 = relu(fbar @ W1 + b1) -> sA (row-pair packed); thread does rows 4h..4h+3
    {
        float w[14];
        #pragma unroll
        for (int d = 0; d < 14; d++) w[d] = sm[OFF_W1 + d * 128 + col];
        const float bb = sm[OFF_B1 + col];
        float acc[4];
        #pragma unroll
        for (int q = 0; q < 4; q++) {
            const int r = 4 * h + q;
            float a = bb;
            #pragma unroll
            for (int d = 0; d < 14; d++) a = fmaf(sF[r * 16 + d], w[d], a);
            acc[q] = fmaxf(a, 0.f);
        }
        reinterpret_cast<float2*>(sA)[(2 * h) * 128 + col]     = make_float2(acc[0], acc[1]);
        reinterpret_cast<float2*>(sA)[(2 * h + 1) * 128 + col] = make_float2(acc[2], acc[3]);
    }
    __syncthreads();

    const ulonglong2* inA2 = reinterpret_cast<const ulonglong2*>(sA + (2 * h) * 256);
    const ulonglong2* inB2 = reinterpret_cast<const ulonglong2*>(sA + (2 * h + 1) * 256);

    // ---- layer 2: h2 = relu(h1 @ W2 + b2), W2 streamed in two chunks ----
    {
        ull accA = 0ULL, accB = 0ULL;
        mbar_wait(mbarB0, 0);
        dense_chunk<16>(inA2, inB2, sm + OFF_W2 + col, 0, accA, accB);
        mbar_wait(mbarB1, 0);
        dense_chunk<16>(inA2, inB2, sm + OFF_W2 + 64 * 128 + col, 16, accA, accB);
        const float bb = sm[OFF_B2 + col];
        float2 vA = upk(accA), vB = upk(accB);
        reinterpret_cast<float2*>(sB)[(2 * h) * 128 + col] =
            make_float2(fmaxf(vA.x + bb, 0.f), fmaxf(vA.y + bb, 0.f));
        reinterpret_cast<float2*>(sB)[(2 * h + 1) * 128 + col] =
            make_float2(fmaxf(vB.x + bb, 0.f), fmaxf(vB.y + bb, 0.f));
    }
    mbar_wait(mbarC, 0);
    __syncthreads();

    // ---- layer 3: m = relu(h2 @ Wm1 + bm1) ----
    {
        const ulonglong2* inA3 = reinterpret_cast<const ulonglong2*>(sB + (2 * h) * 256);
        const ulonglong2* inB3 = reinterpret_cast<const ulonglong2*>(sB + (2 * h + 1) * 256);
        ull accA = 0ULL, accB = 0ULL;
        dense_chunk<32>(inA3, inB3, sm + OFF_WM1 + col, 0, accA, accB);
        const float bb = sm[OFF_BM1 + col];
        float2 vA = upk(accA), vB = upk(accB);
        reinterpret_cast<float2*>(sA)[(2 * h) * 128 + col] =
            make_float2(fmaxf(vA.x + bb, 0.f), fmaxf(vA.y + bb, 0.f));
        reinterpret_cast<float2*>(sA)[(2 * h + 1) * 128 + col] =
            make_float2(fmaxf(vB.x + bb, 0.f), fmaxf(vB.y + bb, 0.f));
    }
    __syncthreads();

    // ---- o = m @ Wm2 + bm2 : 256 threads = 8 rows x 4 cols x 8 k-slices ----
    {
        const int r = tid >> 5, c = (tid >> 3) & 3, s = tid & 7;
        const int pair = r >> 1, e = r & 1;
        float p = 0.f;
        #pragma unroll
        for (int i = 0; i < 16; i++) {
            const int k = s * 16 + i;
            p = fmaf(sA[pair * 256 + 2 * k + e], sm[OFF_WM2 + k * 4 + c], p);
        }
        sP[tid] = p;
    }
    __syncthreads();
    if (tid < ROWS * 4) {
        const int r = tid >> 2, c = tid & 3;
        float o = sm[OFF_BM2 + c];
        #pragma unroll
        for (int s = 0; s < 8; s++) o += sP[(r << 5) | (c << 3) | s];
        sF[r * 16 + c] = o;
    }
    __syncthreads();
    // std computed once per (r, channel): sF[r*16+8+c] = exp(-5+3.5*(tanh+1))
    if (tid < ROWS * 2) {
        const int r = tid >> 1, c = tid & 1;
        const float t = tanhf(sF[r * 16 + 2 + c]);
        sF[r * 16 + 8 + c] = __expf(-5.0f + 3.5f * (t + 1.0f));
    }
    __syncthreads();

    // ---- write: one float4 per thread, fully coalesced ----
    {
        const int plane = tid >> 7;         // 0 = mu, 1 = std
        const int r = (tid & 127) >> 4;     // 0..7
        const int i = tid & 15;             // 0..15
        const int off = plane ? 8 : 0;
        const float v0 = sF[r * 16 + off + 0];
        const float v1 = sF[r * 16 + off + 1];
        float* dst = out + (plane ? (size_t)std_off : 0) + (size_t)(base + r) * 64;
        reinterpret_cast<float4*>(dst)[i] = make_float4(v0, v1, v0, v1);
    }
}

extern "C" void kernel_launch(void* const* d_in, const int* in_sizes, int n_in,
                              void* d_out, int out_size) {
    const float* obs = (const float*)d_in[0];
    const float* W1  = (const float*)d_in[1];
    const float* b1  = (const float*)d_in[2];
    const float* W2  = (const float*)d_in[3];
    const float* b2  = (const float*)d_in[4];
    const float* Wm1 = (const float*)d_in[5];
    const float* bm1 = (const float*)d_in[6];
    const float* Wm2 = (const float*)d_in[7];
    const float* bm2 = (const float*)d_in[8];
    float* out = (float*)d_out;

    const int bs = in_sizes[0] / 512;
    const int std_off = bs * 64;
    const int grid = bs / ROWS;

    cudaFuncSetAttribute(gcnn_actor_kernel,
                         cudaFuncAttributeMaxDynamicSharedMemorySize, SMEM_BYTES);
    gcnn_actor_kernel<<<grid, NT, SMEM_BYTES>>>(obs, W1, b1, W2, b2, Wm1, bm1,
                                                Wm2, bm2, out, std_off);
}